// round 1
// baseline (speedup 1.0000x reference)
#include <cuda_runtime.h>
#include <math.h>

#define BATCH 8
#define TLEN 120000
#define NF 1001
#define FFTL 2048
#define HALF 1024
#define K1 1025
#define KPAD 36
#define CLEN 1097          /* K1 + 2*KPAD */
#define NTH 512

__device__ __forceinline__ float warp_sum(float v) {
#pragma unroll
    for (int o = 16; o; o >>= 1) v += __shfl_down_sync(0xffffffffu, v, o);
    return v;
}

__device__ __forceinline__ int refl_idx(int t) {
    int j = t - KPAD;
    int r = j < 0 ? -j : j;
    if (r > HALF) r = FFTL - r;
    return r;
}

// 1024-point complex Stockham radix-2 FFT (forward, e^{-i...}). 512 threads,
// one butterfly per thread per stage. tw[r] = exp(-i*pi*r/1024).
// After 10 ping-pong stages the result lands back in X.
__device__ __forceinline__ void fft1024(float2* X, float2* Y,
                                        const float2* __restrict__ tw, int tid) {
#pragma unroll
    for (int st = 0; st < 10; st++) {
        int m  = 1 << st;
        int jm = tid & ~(m - 1);          // j*m
        int o  = tid + jm;
        float2 w = tw[jm << 1];           // exp(-i*pi*j/l), l = 512>>st
        float2 a = X[tid];
        float2 b = X[tid + 512];
        float2 s = make_float2(a.x + b.x, a.y + b.y);
        float2 d = make_float2(a.x - b.x, a.y - b.y);
        Y[o]     = s;
        Y[o + m] = make_float2(d.x * w.x - d.y * w.y, d.x * w.y + d.y * w.x);
        __syncthreads();
        float2* t = X; X = Y; Y = t;
    }
}

__device__ __forceinline__ double interpC(const double* __restrict__ C, float pos) {
    int lo = (int)floorf(pos);
    lo = min(max(lo, 0), CLEN - 2);
    double frac = (double)pos - (double)lo;
    double clo = C[lo];
    return clo + (C[lo + 1] - clo) * frac;
}

__global__ __launch_bounds__(NTH)
void cheaptrick_kernel(const float* __restrict__ x, const float* __restrict__ f0in,
                       float* __restrict__ out) {
    __shared__ float2 za[1024];
    __shared__ float2 zb[1024];
    __shared__ float2 tw[1024];
    __shared__ float  fr[2048];
    __shared__ float  sP[1104];
    __shared__ double sC[1100];
    __shared__ float  red[3][16];
    __shared__ double wexcl[16];
    __shared__ float  scal[3];

    const int tid  = threadIdx.x;
    const int lane = tid & 31;
    const int wid  = tid >> 5;
    const int fi   = blockIdx.x;
    const int b    = blockIdx.y;

    float f0v = f0in[b * NF + fi];
    if (f0v <= 35.2078239f) f0v = 500.0f;   // F_MIN = 72000/2045

    // twiddle table: tw[r] = exp(-i*pi*r/1024)
    for (int r = tid; r < 1024; r += NTH) {
        float s, c;
        sincospif(-(float)r * (1.0f / 1024.0f), &s, &c);
        tw[r] = make_float2(c, s);
    }

    // -------- frame load + window sums (S1=sum w, S2=sum w^2, S3=sum v*w) ----
    const float hwl = rintf(36000.0f / f0v);   // round(1.5*fs/f0), half-to-even
    float s1 = 0.f, s2 = 0.f, s3 = 0.f;
    for (int i = tid; i < FFTL; i += NTH) {
        int rel = i - HALF;
        int ix = fi * 120 + rel;
        ix = min(max(ix, 0), TLEN - 1);
        float v = x[b * TLEN + ix];
        fr[i] = v;
        float w = 0.0f;
        if (fabsf((float)rel) <= hwl)
            w = 0.5f * cospif((float)rel * f0v * (1.0f / 36000.0f)) + 0.5f;
        s1 += w; s2 += w * w; s3 += v * w;
    }
    s1 = warp_sum(s1); s2 = warp_sum(s2); s3 = warp_sum(s3);
    if (lane == 0) { red[0][wid] = s1; red[1][wid] = s2; red[2][wid] = s3; }
    __syncthreads();
    if (tid < 32) {
        float a  = (tid < 16) ? red[0][tid] : 0.f;
        float bb = (tid < 16) ? red[1][tid] : 0.f;
        float c  = (tid < 16) ? red[2][tid] : 0.f;
        a = warp_sum(a); bb = warp_sum(bb); c = warp_sum(c);
        if (tid == 0) { scal[0] = a; scal[1] = bb; scal[2] = c; }
    }
    __syncthreads();
    const float invs = 1.0f / sqrtf(scal[1]);
    const float mu   = scal[2] / scal[0];

    // -------- pack wav = win*(frame - mu)*invs into complex pairs ------------
    for (int j = tid; j < 1024; j += NTH) {
        int r0 = 2 * j - HALF, r1 = r0 + 1;
        float w0 = 0.f, w1 = 0.f;
        if (fabsf((float)r0) <= hwl)
            w0 = 0.5f * cospif((float)r0 * f0v * (1.0f / 36000.0f)) + 0.5f;
        if (fabsf((float)r1) <= hwl)
            w1 = 0.5f * cospif((float)r1 * f0v * (1.0f / 36000.0f)) + 0.5f;
        float v0 = w0 * (fr[2 * j]     - mu) * invs;
        float v1 = w1 * (fr[2 * j + 1] - mu) * invs;
        za[j] = make_float2(v0, v1);
    }
    __syncthreads();

    fft1024(za, zb, tw, tid);

    // -------- untangle rfft -> power spectrum P[0..1024] ---------------------
    for (int k = tid; k < 1024; k += NTH) {
        float2 Zk = za[k];
        float2 Zm = za[(1024 - k) & 1023];
        float Er = 0.5f * (Zk.x + Zm.x);
        float Ei = 0.5f * (Zk.y - Zm.y);
        float Or = 0.5f * (Zk.y + Zm.y);
        float Oi = 0.5f * (Zm.x - Zk.x);
        float2 w = tw[k];
        float Xr = Er + w.x * Or - w.y * Oi;
        float Xi = Ei + w.x * Oi + w.y * Or;
        sP[k] = Xr * Xr + Xi * Xi;
    }
    if (tid == 0) {
        float2 Z0 = za[0];
        float v = Z0.x - Z0.y;
        sP[1024] = v * v;
    }
    __syncthreads();

    // -------- DC-band replication -------------------------------------------
    const float rate = f0v * (2048.0f / 24000.0f);
    const int  kmax  = (int)floorf(rate);
    float repl = 0.f;
    const bool dorep = (tid <= kmax);   // kmax <= 51 << 512
    if (dorep) {
        float m = rate - (float)tid;
        int lo = (int)floorf(m);
        lo = min(max(lo, 0), K1 - 2);
        float fc = m - (float)lo;
        repl = sP[lo] * (1.f - fc) + sP[lo + 1] * fc;
    }
    __syncthreads();
    if (dorep) sP[tid] += repl;
    __syncthreads();

    // -------- reflected cumsum (double) over CLEN=1097 elements --------------
    {
        const double scl = 24000.0 / 2048.0;
        int e0 = tid * 3;
        double q0 = 0, q1 = 0, q2 = 0;
        if (e0     < CLEN) q0 = (double)sP[refl_idx(e0)]     * scl;
        if (e0 + 1 < CLEN) q1 = (double)sP[refl_idx(e0 + 1)] * scl;
        if (e0 + 2 < CLEN) q2 = (double)sP[refl_idx(e0 + 2)] * scl;
        double p0 = q0, p1 = q0 + q1, p2 = q0 + q1 + q2;
        double ts = p2, s = ts;
#pragma unroll
        for (int o = 1; o < 32; o <<= 1) {
            double n = __shfl_up_sync(0xffffffffu, s, o);
            if (lane >= o) s += n;
        }
        if (lane == 31) wexcl[wid] = s;
        __syncthreads();
        if (tid == 0) {
            double acc = 0;
            for (int i = 0; i < 16; i++) { double t = wexcl[i]; wexcl[i] = acc; acc += t; }
        }
        __syncthreads();
        double off = wexcl[wid] + (s - ts);
        if (e0     < CLEN) sC[e0]     = off + p0;
        if (e0 + 1 < CLEN) sC[e0 + 1] = off + p1;
        if (e0 + 2 < CLEN) sC[e0 + 2] = off + p2;
        __syncthreads();
    }

    // -------- f0-adaptive smoothing + log -> G in sP -------------------------
    {
        const float wbins    = f0v * (2.0f / 3.0f) * (2048.0f / 24000.0f);
        const float invwidth = 1.0f / (f0v * (2.0f / 3.0f));
        for (int k = tid; k < K1; k += NTH) {
            float plo = (float)k - 0.5f * wbins + ((float)KPAD - 0.5f);
            float phi = plo + wbins;
            double ilo = interpC(sC, plo);
            double ihi = interpC(sC, phi);
            float Ps = (float)(ihi - ilo) * invwidth;
            Ps = fmaxf(Ps, 1e-30f);
            sP[k] = logf(Ps);
        }
        __syncthreads();
    }

    // -------- cepstrum: FFT of even extension of G, /2048, * sinc * cl -------
    for (int j = tid; j < 1024; j += NTH) {
        int i0 = 2 * j, i1 = 2 * j + 1;
        float g0 = sP[i0 <= HALF ? i0 : FFTL - i0];
        float g1 = sP[i1 <= HALF ? i1 : FFTL - i1];
        za[j] = make_float2(g0, g1);
    }
    __syncthreads();
    fft1024(za, zb, tw, tid);

    const float inv2048 = 1.0f / 2048.0f;
    const float PIF = 3.14159265358979f;
    for (int k = tid; k < 1024; k += NTH) {
        float2 Zk = za[k];
        float2 Zm = za[(1024 - k) & 1023];
        float Er = 0.5f * (Zk.x + Zm.x);
        float Or = 0.5f * (Zk.y + Zm.y);
        float Oi = 0.5f * (Zm.x - Zk.x);
        float2 w = tw[k];
        float Xr = Er + w.x * Or - w.y * Oi;
        float cep = Xr * inv2048;
        float z = f0v * (float)k * (1.0f / 24000.0f);
        float sl = (k == 0) ? 1.0f : (sinpif(z) / (PIF * z));
        float cl = 1.3f - 0.3f * cospif(2.0f * z);
        sP[k] = cep * sl * cl;
    }
    if (tid == 0) {
        float2 Z0 = za[0];
        float cep = (Z0.x - Z0.y) * inv2048;
        float z = f0v * 1024.0f * (1.0f / 24000.0f);
        float sl = sinpif(z) / (PIF * z);
        float cl = 1.3f - 0.3f * cospif(2.0f * z);
        sP[1024] = cep * sl * cl;
    }
    __syncthreads();

    // -------- hfft: FFT of even extension of c -> output ---------------------
    for (int j = tid; j < 1024; j += NTH) {
        int i0 = 2 * j, i1 = 2 * j + 1;
        float g0 = sP[i0 <= HALF ? i0 : FFTL - i0];
        float g1 = sP[i1 <= HALF ? i1 : FFTL - i1];
        za[j] = make_float2(g0, g1);
    }
    __syncthreads();
    fft1024(za, zb, tw, tid);

    float* op = out + ((size_t)b * NF + fi) * K1;
    for (int k = tid; k < 1024; k += NTH) {
        float2 Zk = za[k];
        float2 Zm = za[(1024 - k) & 1023];
        float Er = 0.5f * (Zk.x + Zm.x);
        float Or = 0.5f * (Zk.y + Zm.y);
        float Oi = 0.5f * (Zm.x - Zk.x);
        float2 w = tw[k];
        op[k] = Er + w.x * Or - w.y * Oi;
    }
    if (tid == 0) {
        float2 Z0 = za[0];
        op[1024] = Z0.x - Z0.y;
    }
}

extern "C" void kernel_launch(void* const* d_in, const int* in_sizes, int n_in,
                              void* d_out, int out_size) {
    (void)in_sizes; (void)n_in; (void)out_size;
    const float* x  = (const float*)d_in[0];
    const float* f0 = (const float*)d_in[1];
    float* out = (float*)d_out;
    dim3 grid(NF, BATCH);
    cheaptrick_kernel<<<grid, NTH>>>(x, f0, out);
}

// round 2
// speedup vs baseline: 1.1785x; 1.1785x over previous
#include <cuda_runtime.h>
#include <math.h>

#define BATCH 8
#define TLEN 120000
#define NF 1001
#define FFTL 2048
#define HALF 1024
#define K1 1025
#define KPAD 36
#define CLEN 1097          /* K1 + 2*KPAD */
#define NTH 512
#define SBT 256            /* threads per sub-block (frame) */

/* dynamic smem layout (bytes):
   za   float2[2][1024]   @ 0      (16384)
   zb   float2[2][1024]   @ 16384  (16384)   -- also holds window during setup
   tw   float2[1024]      @ 32768  (8192)
   sC   double[2][1100]   @ 40960  (17600)   -- fr (float[2048]) aliases each frame's block
   sP   float[2][1104]    @ 58560  (8832)
   wexcl double[2][8]     @ 67392  (128)
   red  float[2][3][8]    @ 67520  (192)
   scal float[2][4]       @ 67712  (32)
   total 67744 */
#define SMEM_BYTES 67744

__device__ __forceinline__ float warp_sum(float v) {
#pragma unroll
    for (int o = 16; o; o >>= 1) v += __shfl_down_sync(0xffffffffu, v, o);
    return v;
}

__device__ __forceinline__ float2 cmul(float2 a, float2 b) {
    return make_float2(a.x * b.x - a.y * b.y, a.x * b.y + a.y * b.x);
}

__device__ __forceinline__ int refl_idx(int t) {
    int j = t - KPAD;
    int r = j < 0 ? -j : j;
    if (r > HALF) r = FFTL - r;
    return r;
}

// 1024-point complex forward FFT, radix-4 Stockham (fused pairs of the verified
// radix-2 stages). 256 threads (r = sub-thread id), 5 stages, result lands in Y.
// tw[x] = exp(-i*pi*x/1024);  W = exp(-2*pi*i/1024) = tw[2].
// Derivation from radix-2 stages (s, s+1), m = 2^s:
//   base = 4*jm + q,  jm = r & ~(m-1), q = r & (m-1)
//   Z[base]    = (A0+A2) + (A1+A3)
//   Z[base+m]  = ((A0-A2) - i(A1-A3)) * W^jm
//   Z[base+2m] = ((A0+A2) - (A1+A3)) * W^{2jm}
//   Z[base+3m] = ((A0-A2) + i(A1-A3)) * W^{3jm}
__device__ __forceinline__ void fft1024r4(float2* X, float2* Y,
                                          const float2* __restrict__ tw, int r) {
#pragma unroll
    for (int stg = 0; stg < 5; stg++) {
        int m  = 1 << (2 * stg);
        int q  = r & (m - 1);
        int jm = r - q;
        int base = 4 * jm + q;
        float2 w1 = tw[2 * jm];       // W^jm   (2*jm <= 510)
        float2 w2 = tw[4 * jm];       // W^2jm  (4*jm <= 1020)
        float2 w3 = cmul(w1, w2);
        float2 a0 = X[r], a1 = X[r + 256], a2 = X[r + 512], a3 = X[r + 768];
        float2 b0 = make_float2(a0.x + a2.x, a0.y + a2.y);
        float2 b1 = make_float2(a0.x - a2.x, a0.y - a2.y);
        float2 b2 = make_float2(a1.x + a3.x, a1.y + a3.y);
        float2 b3 = make_float2(a1.x - a3.x, a1.y - a3.y);
        float2 t1 = make_float2(b1.x + b3.y, b1.y - b3.x);   // b1 - i*b3
        float2 t3 = make_float2(b1.x - b3.y, b1.y + b3.x);   // b1 + i*b3
        Y[base]         = make_float2(b0.x + b2.x, b0.y + b2.y);
        Y[base + m]     = cmul(t1, w1);
        Y[base + 2 * m] = cmul(make_float2(b0.x - b2.x, b0.y - b2.y), w2);
        Y[base + 3 * m] = cmul(t3, w3);
        __syncthreads();
        float2* t = X; X = Y; Y = t;
    }
}

__device__ __forceinline__ double interpC(const double* __restrict__ C, float pos) {
    int lo = (int)floorf(pos);
    lo = min(max(lo, 0), CLEN - 2);
    double frac = (double)pos - (double)lo;
    double clo = C[lo];
    return clo + (C[lo + 1] - clo) * frac;
}

__global__ __launch_bounds__(NTH, 3)
void cheaptrick_kernel(const float* __restrict__ x, const float* __restrict__ f0in,
                       float* __restrict__ out) {
    extern __shared__ char smem[];

    const int tid  = threadIdx.x;
    const int sub  = tid >> 8;          // which frame within the CTA
    const int st   = tid & 255;         // sub-thread id
    const int lane = tid & 31;
    const int w8   = st >> 5;           // warp within sub-block, 0..7
    const int bx   = blockIdx.x;
    const int b    = blockIdx.y;

    float2* za  = (float2*)(smem)          + sub * 1024;
    float2* zb  = (float2*)(smem + 16384)  + sub * 1024;
    float2* tw  = (float2*)(smem + 32768);
    double* sC  = (double*)(smem + 40960)  + sub * 1100;
    float*  fr  = (float*)(smem + 40960 + sub * 8800);   // aliases sC block
    float*  sP  = (float*)(smem + 58560)   + sub * 1104;
    double* wex = (double*)(smem + 67392)  + sub * 8;
    float*  red = (float*)(smem + 67520)   + sub * 24;   // [3][8]
    float*  scl = (float*)(smem + 67712)   + sub * 4;

    int fi = bx * 2 + sub;
    const bool dostore = (fi < NF);
    if (!dostore) fi = NF - 1;

    float f0v = f0in[b * NF + fi];
    if (f0v <= 35.2078239f) f0v = 500.0f;   // F_MIN = 72000/2045

    // twiddle table: tw[r] = exp(-i*pi*r/1024) — shared by both frames
    for (int r = tid; r < 1024; r += NTH) {
        float s, c;
        sincospif(-(float)r * (1.0f / 1024.0f), &s, &c);
        tw[r] = make_float2(c, s);
    }

    // -------- frame load + window + sums (S1=sum w, S2=sum w^2, S3=sum v*w) --
    const float hwl = rintf(36000.0f / f0v);   // round(1.5*fs/f0)
    float* wbuf = (float*)zb;                  // stash window in zb (dead until FFT)
    float s1 = 0.f, s2 = 0.f, s3 = 0.f;
    for (int i = st; i < FFTL; i += SBT) {
        int rel = i - HALF;
        int ix = min(max(fi * 120 + rel, 0), TLEN - 1);
        float v = x[b * TLEN + ix];
        fr[i] = v;
        float w = 0.0f;
        if (fabsf((float)rel) <= hwl)
            w = 0.5f * cospif((float)rel * f0v * (1.0f / 36000.0f)) + 0.5f;
        wbuf[i] = w;
        s1 += w; s2 += w * w; s3 += v * w;
    }
    s1 = warp_sum(s1); s2 = warp_sum(s2); s3 = warp_sum(s3);
    if (lane == 0) { red[w8] = s1; red[8 + w8] = s2; red[16 + w8] = s3; }
    __syncthreads();
    if (st == 0) {
        float a = 0.f, bb = 0.f, c = 0.f;
#pragma unroll
        for (int i = 0; i < 8; i++) { a += red[i]; bb += red[8 + i]; c += red[16 + i]; }
        scl[0] = a; scl[1] = bb; scl[2] = c;
    }
    __syncthreads();
    const float invs = 1.0f / sqrtf(scl[1]);
    const float mu   = scl[2] / scl[0];

    // -------- pack wav = win*(frame - mu)*invs into complex pairs ------------
    for (int j = st; j < 1024; j += SBT) {
        float v0 = wbuf[2 * j]     * (fr[2 * j]     - mu) * invs;
        float v1 = wbuf[2 * j + 1] * (fr[2 * j + 1] - mu) * invs;
        za[j] = make_float2(v0, v1);
    }
    __syncthreads();

    fft1024r4(za, zb, tw, st);          // result in zb

    // -------- untangle rfft -> power spectrum P[0..1024] ---------------------
    for (int k = st; k < 1024; k += SBT) {
        float2 Zk = zb[k];
        float2 Zm = zb[(1024 - k) & 1023];
        float Er = 0.5f * (Zk.x + Zm.x);
        float Ei = 0.5f * (Zk.y - Zm.y);
        float Or = 0.5f * (Zk.y + Zm.y);
        float Oi = 0.5f * (Zm.x - Zk.x);
        float2 w = tw[k];
        float Xr = Er + w.x * Or - w.y * Oi;
        float Xi = Ei + w.x * Oi + w.y * Or;
        sP[k] = Xr * Xr + Xi * Xi;
    }
    if (st == 0) {
        float2 Z0 = zb[0];
        float v = Z0.x - Z0.y;
        sP[1024] = v * v;
    }
    __syncthreads();

    // -------- DC-band replication -------------------------------------------
    const float rate = f0v * (2048.0f / 24000.0f);
    const int  kmax  = (int)floorf(rate);       // <= 51 << 256
    float repl = 0.f;
    const bool dorep = (st <= kmax);
    if (dorep) {
        float m = rate - (float)st;
        int lo = (int)floorf(m);
        lo = min(max(lo, 0), K1 - 2);
        float fc = m - (float)lo;
        repl = sP[lo] * (1.f - fc) + sP[lo + 1] * fc;
    }
    __syncthreads();
    if (dorep) sP[st] += repl;
    __syncthreads();

    // -------- reflected cumsum (double) over CLEN=1097 elements --------------
    {
        const double sclr = 24000.0 / 2048.0;
        int e0 = st * 5;                         // 5 elems/thread, 1280 >= 1097
        double pp[5];
        double acc = 0.0;
#pragma unroll
        for (int i = 0; i < 5; i++) {
            int e = e0 + i;
            double qv = (e < CLEN) ? (double)sP[refl_idx(e)] * sclr : 0.0;
            acc += qv;
            pp[i] = acc;
        }
        double ts = acc, s = ts;
#pragma unroll
        for (int o = 1; o < 32; o <<= 1) {
            double n = __shfl_up_sync(0xffffffffu, s, o);
            if (lane >= o) s += n;
        }
        if (lane == 31) wex[w8] = s;
        __syncthreads();
        if (st == 0) {
            double a = 0.0;
#pragma unroll
            for (int i = 0; i < 8; i++) { double t = wex[i]; wex[i] = a; a += t; }
        }
        __syncthreads();
        double off = wex[w8] + (s - ts);
#pragma unroll
        for (int i = 0; i < 5; i++) {
            int e = e0 + i;
            if (e < CLEN) sC[e] = off + pp[i];
        }
        __syncthreads();
    }

    // -------- f0-adaptive smoothing + log -> G in sP -------------------------
    {
        const float wbins    = f0v * (2.0f / 3.0f) * (2048.0f / 24000.0f);
        const float invwidth = 1.0f / (f0v * (2.0f / 3.0f));
        for (int k = st; k < K1; k += SBT) {
            float plo = (float)k - 0.5f * wbins + ((float)KPAD - 0.5f);
            float phi = plo + wbins;
            double ilo = interpC(sC, plo);
            double ihi = interpC(sC, phi);
            float Ps = (float)(ihi - ilo) * invwidth;
            Ps = fmaxf(Ps, 1e-30f);
            sP[k] = logf(Ps);
        }
        __syncthreads();
    }

    // -------- cepstrum: FFT of even extension of G, /2048, * sinc * cl -------
    for (int j = st; j < 1024; j += SBT) {
        int i0 = 2 * j, i1 = 2 * j + 1;
        float g0 = sP[i0 <= HALF ? i0 : FFTL - i0];
        float g1 = sP[i1 <= HALF ? i1 : FFTL - i1];
        za[j] = make_float2(g0, g1);
    }
    __syncthreads();
    fft1024r4(za, zb, tw, st);          // result in zb

    const float inv2048 = 1.0f / 2048.0f;
    const float PIF = 3.14159265358979f;
    for (int k = st; k < 1024; k += SBT) {
        float2 Zk = zb[k];
        float2 Zm = zb[(1024 - k) & 1023];
        float Er = 0.5f * (Zk.x + Zm.x);
        float Or = 0.5f * (Zk.y + Zm.y);
        float Oi = 0.5f * (Zm.x - Zk.x);
        float2 w = tw[k];
        float Xr = Er + w.x * Or - w.y * Oi;
        float cep = Xr * inv2048;
        float z = f0v * (float)k * (1.0f / 24000.0f);
        float sl = (k == 0) ? 1.0f : (sinpif(z) / (PIF * z));
        float cl = 1.3f - 0.3f * cospif(2.0f * z);
        sP[k] = cep * sl * cl;
    }
    if (st == 0) {
        float2 Z0 = zb[0];
        float cep = (Z0.x - Z0.y) * inv2048;
        float z = f0v * 1024.0f * (1.0f / 24000.0f);
        float sl = sinpif(z) / (PIF * z);
        float cl = 1.3f - 0.3f * cospif(2.0f * z);
        sP[1024] = cep * sl * cl;
    }
    __syncthreads();

    // -------- hfft: FFT of even extension of c -> output ---------------------
    for (int j = st; j < 1024; j += SBT) {
        int i0 = 2 * j, i1 = 2 * j + 1;
        float g0 = sP[i0 <= HALF ? i0 : FFTL - i0];
        float g1 = sP[i1 <= HALF ? i1 : FFTL - i1];
        za[j] = make_float2(g0, g1);
    }
    __syncthreads();
    fft1024r4(za, zb, tw, st);          // result in zb

    float* op = out + ((size_t)b * NF + fi) * K1;
    for (int k = st; k < 1024; k += SBT) {
        float2 Zk = zb[k];
        float2 Zm = zb[(1024 - k) & 1023];
        float Er = 0.5f * (Zk.x + Zm.x);
        float Or = 0.5f * (Zk.y + Zm.y);
        float Oi = 0.5f * (Zm.x - Zk.x);
        float2 w = tw[k];
        if (dostore) op[k] = Er + w.x * Or - w.y * Oi;
    }
    if (st == 0 && dostore) {
        float2 Z0 = zb[0];
        op[1024] = Z0.x - Z0.y;
    }
}

extern "C" void kernel_launch(void* const* d_in, const int* in_sizes, int n_in,
                              void* d_out, int out_size) {
    (void)in_sizes; (void)n_in; (void)out_size;
    const float* x  = (const float*)d_in[0];
    const float* f0 = (const float*)d_in[1];
    float* out = (float*)d_out;
    cudaFuncSetAttribute(cheaptrick_kernel,
                         cudaFuncAttributeMaxDynamicSharedMemorySize, SMEM_BYTES);
    dim3 grid((NF + 1) / 2, BATCH);
    cheaptrick_kernel<<<grid, NTH, SMEM_BYTES>>>(x, f0, out);
}

// round 3
// speedup vs baseline: 1.2015x; 1.0195x over previous
#include <cuda_runtime.h>
#include <math.h>

#define BATCH 8
#define TLEN 120000
#define NF 1001
#define FFTL 2048
#define HALF 1024
#define K1 1025
#define KPAD 36
#define CLEN 1097          /* K1 + 2*KPAD */
#define NTH 512
#define SBT 256            /* threads per sub-block (frame) */

#define SMEM_BYTES 67744

__device__ float2 g_tw[1024];
__device__ float  g_invk[1025];

__global__ void init_tables() {
    int i = blockIdx.x * blockDim.x + threadIdx.x;
    if (i < 1024) {
        float s, c;
        sincospif(-(float)i * (1.0f / 1024.0f), &s, &c);
        g_tw[i] = make_float2(c, s);
    }
    if (i <= 1024) g_invk[i] = (i == 0) ? 0.0f : 1.0f / (float)i;
}

__device__ __forceinline__ float warp_sum(float v) {
#pragma unroll
    for (int o = 16; o; o >>= 1) v += __shfl_down_sync(0xffffffffu, v, o);
    return v;
}

__device__ __forceinline__ float2 cmul(float2 a, float2 b) {
    return make_float2(a.x * b.x - a.y * b.y, a.x * b.y + a.y * b.x);
}

__device__ __forceinline__ int refl_idx(int t) {
    int j = t - KPAD;
    int r = j < 0 ? -j : j;
    if (r > HALF) r = FFTL - r;
    return r;
}

// 1024-point complex forward FFT, radix-4 Stockham. 256 threads, 5 stages,
// result lands in Y. tw[x] = exp(-i*pi*x/1024).
__device__ __forceinline__ void fft1024r4(float2* X, float2* Y,
                                          const float2* __restrict__ tw, int r) {
#pragma unroll
    for (int stg = 0; stg < 5; stg++) {
        int m  = 1 << (2 * stg);
        int q  = r & (m - 1);
        int jm = r - q;
        int base = 4 * jm + q;
        float2 w1 = tw[2 * jm];
        float2 w2 = tw[4 * jm];
        float2 w3 = cmul(w1, w2);
        float2 a0 = X[r], a1 = X[r + 256], a2 = X[r + 512], a3 = X[r + 768];
        float2 b0 = make_float2(a0.x + a2.x, a0.y + a2.y);
        float2 b1 = make_float2(a0.x - a2.x, a0.y - a2.y);
        float2 b2 = make_float2(a1.x + a3.x, a1.y + a3.y);
        float2 b3 = make_float2(a1.x - a3.x, a1.y - a3.y);
        float2 t1 = make_float2(b1.x + b3.y, b1.y - b3.x);
        float2 t3 = make_float2(b1.x - b3.y, b1.y + b3.x);
        Y[base]         = make_float2(b0.x + b2.x, b0.y + b2.y);
        Y[base + m]     = cmul(t1, w1);
        Y[base + 2 * m] = cmul(make_float2(b0.x - b2.x, b0.y - b2.y), w2);
        Y[base + 3 * m] = cmul(t3, w3);
        __syncthreads();
        float2* t = X; X = Y; Y = t;
    }
}

__device__ __forceinline__ double interpC(const double* __restrict__ C, float pos) {
    int lo = (int)floorf(pos);
    lo = min(max(lo, 0), CLEN - 2);
    double frac = (double)pos - (double)lo;
    double clo = C[lo];
    return clo + (C[lo + 1] - clo) * frac;
}

__global__ __launch_bounds__(NTH, 3)
void cheaptrick_kernel(const float* __restrict__ x, const float* __restrict__ f0in,
                       float* __restrict__ out) {
    extern __shared__ char smem[];

    const int tid  = threadIdx.x;
    const int sub  = tid >> 8;
    const int st   = tid & 255;
    const int lane = tid & 31;
    const int w8   = st >> 5;
    const int bx   = blockIdx.x;
    const int b    = blockIdx.y;

    float2* za  = (float2*)(smem)          + sub * 1024;
    float2* zb  = (float2*)(smem + 16384)  + sub * 1024;
    float2* tw  = (float2*)(smem + 32768);
    double* sC  = (double*)(smem + 40960)  + sub * 1100;
    float*  fr  = (float*)(smem + 40960 + sub * 8800);   // aliases sC block
    float*  sP  = (float*)(smem + 58560)   + sub * 1104;
    double* wex = (double*)(smem + 67392)  + sub * 8;
    float*  red = (float*)(smem + 67520)   + sub * 24;
    float*  scl = (float*)(smem + 67712)   + sub * 4;

    int fi = bx * 2 + sub;
    const bool dostore = (fi < NF);
    if (!dostore) fi = NF - 1;

    float f0v = f0in[b * NF + fi];
    if (f0v <= 35.2078239f) f0v = 500.0f;   // F_MIN = 72000/2045

    // twiddle table from global (no MUFU)
    for (int r = tid; r < 1024; r += NTH) tw[r] = g_tw[r];

    // -------- frame load + window (rotation recurrence) + sums ---------------
    const float hwl = rintf(36000.0f / f0v);
    float* wbuf = (float*)zb;
    float s1 = 0.f, s2 = 0.f, s3 = 0.f;
    {
        float c0, s0, cd, sd;
        sincospif((float)(st - HALF) * f0v * (1.0f / 36000.0f), &s0, &c0);
        sincospif(256.0f * f0v * (1.0f / 36000.0f), &sd, &cd);
#pragma unroll
        for (int ii = 0; ii < 8; ii++) {
            int i = st + ii * 256;
            int rel = i - HALF;
            int ix = min(max(fi * 120 + rel, 0), TLEN - 1);
            float v = x[b * TLEN + ix];
            fr[i] = v;
            float w = (fabsf((float)rel) <= hwl) ? fmaf(0.5f, c0, 0.5f) : 0.0f;
            wbuf[i] = w;
            s1 += w; s2 += w * w; s3 += v * w;
            float cn = c0 * cd - s0 * sd;
            s0 = s0 * cd + c0 * sd;
            c0 = cn;
        }
    }
    s1 = warp_sum(s1); s2 = warp_sum(s2); s3 = warp_sum(s3);
    if (lane == 0) { red[w8] = s1; red[8 + w8] = s2; red[16 + w8] = s3; }
    __syncthreads();
    if (st == 0) {
        float a = 0.f, bb = 0.f, c = 0.f;
#pragma unroll
        for (int i = 0; i < 8; i++) { a += red[i]; bb += red[8 + i]; c += red[16 + i]; }
        scl[0] = a; scl[1] = bb; scl[2] = c;
    }
    __syncthreads();
    const float invs = 1.0f / sqrtf(scl[1]);
    const float mu   = scl[2] / scl[0];

    // -------- pack wav = win*(frame - mu)*invs -------------------------------
    for (int j = st; j < 1024; j += SBT) {
        float v0 = wbuf[2 * j]     * (fr[2 * j]     - mu) * invs;
        float v1 = wbuf[2 * j + 1] * (fr[2 * j + 1] - mu) * invs;
        za[j] = make_float2(v0, v1);
    }
    __syncthreads();

    fft1024r4(za, zb, tw, st);          // result in zb

    // -------- untangle rfft -> power spectrum --------------------------------
    for (int k = st; k < 1024; k += SBT) {
        float2 Zk = zb[k];
        float2 Zm = zb[(1024 - k) & 1023];
        float Er = 0.5f * (Zk.x + Zm.x);
        float Ei = 0.5f * (Zk.y - Zm.y);
        float Or = 0.5f * (Zk.y + Zm.y);
        float Oi = 0.5f * (Zm.x - Zk.x);
        float2 w = tw[k];
        float Xr = Er + w.x * Or - w.y * Oi;
        float Xi = Ei + w.x * Oi + w.y * Or;
        sP[k] = Xr * Xr + Xi * Xi;
    }
    if (st == 0) {
        float2 Z0 = zb[0];
        float v = Z0.x - Z0.y;
        sP[1024] = v * v;
    }
    __syncthreads();

    // -------- DC-band replication -------------------------------------------
    const float rate = f0v * (2048.0f / 24000.0f);
    const int  kmax  = (int)floorf(rate);
    float repl = 0.f;
    const bool dorep = (st <= kmax);
    if (dorep) {
        float m = rate - (float)st;
        int lo = (int)floorf(m);
        lo = min(max(lo, 0), K1 - 2);
        float fc = m - (float)lo;
        repl = sP[lo] * (1.f - fc) + sP[lo + 1] * fc;
    }
    __syncthreads();
    if (dorep) sP[st] += repl;
    __syncthreads();

    // -------- reflected cumsum (double) --------------------------------------
    {
        const double sclr = 24000.0 / 2048.0;
        int e0 = st * 5;
        double pp[5];
        double acc = 0.0;
#pragma unroll
        for (int i = 0; i < 5; i++) {
            int e = e0 + i;
            double qv = (e < CLEN) ? (double)sP[refl_idx(e)] * sclr : 0.0;
            acc += qv;
            pp[i] = acc;
        }
        double ts = acc, s = ts;
#pragma unroll
        for (int o = 1; o < 32; o <<= 1) {
            double n = __shfl_up_sync(0xffffffffu, s, o);
            if (lane >= o) s += n;
        }
        if (lane == 31) wex[w8] = s;
        __syncthreads();
        if (st == 0) {
            double a = 0.0;
#pragma unroll
            for (int i = 0; i < 8; i++) { double t = wex[i]; wex[i] = a; a += t; }
        }
        __syncthreads();
        double off = wex[w8] + (s - ts);
#pragma unroll
        for (int i = 0; i < 5; i++) {
            int e = e0 + i;
            if (e < CLEN) sC[e] = off + pp[i];
        }
        __syncthreads();
    }

    // -------- f0-adaptive smoothing + log ------------------------------------
    {
        const float wbins    = f0v * (2.0f / 3.0f) * (2048.0f / 24000.0f);
        const float invwidth = 1.0f / (f0v * (2.0f / 3.0f));
        for (int k = st; k < K1; k += SBT) {
            float plo = (float)k - 0.5f * wbins + ((float)KPAD - 0.5f);
            float phi = plo + wbins;
            double ilo = interpC(sC, plo);
            double ihi = interpC(sC, phi);
            float Ps = (float)(ihi - ilo) * invwidth;
            Ps = fmaxf(Ps, 1e-30f);
            sP[k] = __logf(Ps);
        }
        __syncthreads();
    }

    // -------- cepstrum FFT ---------------------------------------------------
    for (int j = st; j < 1024; j += SBT) {
        int i0 = 2 * j, i1 = 2 * j + 1;
        float g0 = sP[i0 <= HALF ? i0 : FFTL - i0];
        float g1 = sP[i1 <= HALF ? i1 : FFTL - i1];
        za[j] = make_float2(g0, g1);
    }
    __syncthreads();
    fft1024r4(za, zb, tw, st);          // result in zb

    // -------- liftering (rotation recurrence: sl = sin/(pi z), cl = 1+0.6 sin^2)
    const float inv2048 = 1.0f / 2048.0f;
    {
        float ls, lc, lds, ldc;
        sincospif(f0v * (float)st * (1.0f / 24000.0f), &ls, &lc);
        sincospif(f0v * 256.0f * (1.0f / 24000.0f), &lds, &ldc);
        const float slf = 24000.0f / (3.14159265358979f * f0v);
#pragma unroll
        for (int ii = 0; ii < 4; ii++) {
            int k = st + ii * 256;
            float2 Zk = zb[k];
            float2 Zm = zb[(1024 - k) & 1023];
            float Er = 0.5f * (Zk.x + Zm.x);
            float Or = 0.5f * (Zk.y + Zm.y);
            float Oi = 0.5f * (Zm.x - Zk.x);
            float2 w = tw[k];
            float Xr = Er + w.x * Or - w.y * Oi;
            float cep = Xr * inv2048;
            float sl = (k == 0) ? 1.0f : ls * slf * g_invk[k];
            float cl = fmaf(0.6f, ls * ls, 1.0f);
            sP[k] = cep * sl * cl;
            float cn = lc * ldc - ls * lds;
            ls = ls * ldc + lc * lds;
            lc = cn;
        }
    }
    if (st == 0) {
        float2 Z0 = zb[0];
        float cep = (Z0.x - Z0.y) * inv2048;
        float z = f0v * 1024.0f * (1.0f / 24000.0f);
        float sn = sinpif(z);
        float sl = sn / (3.14159265358979f * z);
        float cl = fmaf(0.6f, sn * sn, 1.0f);
        sP[1024] = cep * sl * cl;
    }
    __syncthreads();

    // -------- hfft -----------------------------------------------------------
    for (int j = st; j < 1024; j += SBT) {
        int i0 = 2 * j, i1 = 2 * j + 1;
        float g0 = sP[i0 <= HALF ? i0 : FFTL - i0];
        float g1 = sP[i1 <= HALF ? i1 : FFTL - i1];
        za[j] = make_float2(g0, g1);
    }
    __syncthreads();
    fft1024r4(za, zb, tw, st);          // result in zb

    float* op = out + ((size_t)b * NF + fi) * K1;
    for (int k = st; k < 1024; k += SBT) {
        float2 Zk = zb[k];
        float2 Zm = zb[(1024 - k) & 1023];
        float Er = 0.5f * (Zk.x + Zm.x);
        float Or = 0.5f * (Zk.y + Zm.y);
        float Oi = 0.5f * (Zm.x - Zk.x);
        float2 w = tw[k];
        if (dostore) op[k] = Er + w.x * Or - w.y * Oi;
    }
    if (st == 0 && dostore) {
        float2 Z0 = zb[0];
        op[1024] = Z0.x - Z0.y;
    }
}

extern "C" void kernel_launch(void* const* d_in, const int* in_sizes, int n_in,
                              void* d_out, int out_size) {
    (void)in_sizes; (void)n_in; (void)out_size;
    const float* x  = (const float*)d_in[0];
    const float* f0 = (const float*)d_in[1];
    float* out = (float*)d_out;
    init_tables<<<5, 256>>>();
    cudaFuncSetAttribute(cheaptrick_kernel,
                         cudaFuncAttributeMaxDynamicSharedMemorySize, SMEM_BYTES);
    dim3 grid((NF + 1) / 2, BATCH);
    cheaptrick_kernel<<<grid, NTH, SMEM_BYTES>>>(x, f0, out);
}

// round 4
// speedup vs baseline: 2.1262x; 1.7697x over previous
#include <cuda_runtime.h>
#include <math.h>

#define BATCH 8
#define TLEN 120000
#define NF 1001
#define FFTL 2048
#define HALF 1024
#define K1 1025
#define KPAD 36
#define CLEN 1097          /* K1 + 2*KPAD */
#define NTH 512
#define SBT 256            /* threads per sub-block (frame) */

/* dynamic smem layout (bytes):
   za  float2[2][1024] @ 0      (16384)  -- sC float[1097] aliases per-frame half later
   zb  float2[2][1024] @ 16384  (16384)
   tw  float2[1024]    @ 32768  (8192)
   sP  float[2][1032]  @ 40960  (8256)
   wex float[2][8]     @ 49216  (64)
   red float[2][24]    @ 49280  (192)
   scl float[2][4]     @ 49472  (32)
   total 49504 -> 4 CTAs/SM */
#define SMEM_BYTES 49504

__device__ float2 g_tw[1024];
__device__ float  g_invk[1025];

__global__ void init_tables() {
    int i = blockIdx.x * blockDim.x + threadIdx.x;
    if (i < 1024) {
        float s, c;
        sincospif(-(float)i * (1.0f / 1024.0f), &s, &c);
        g_tw[i] = make_float2(c, s);
    }
    if (i <= 1024) g_invk[i] = (i == 0) ? 0.0f : 1.0f / (float)i;
}

__device__ __forceinline__ float warp_sum(float v) {
#pragma unroll
    for (int o = 16; o; o >>= 1) v += __shfl_down_sync(0xffffffffu, v, o);
    return v;
}

__device__ __forceinline__ float2 cmul(float2 a, float2 b) {
    return make_float2(a.x * b.x - a.y * b.y, a.x * b.y + a.y * b.x);
}

__device__ __forceinline__ int refl_idx(int t) {
    int j = t - KPAD;
    int r = j < 0 ? -j : j;
    if (r > HALF) r = FFTL - r;
    return r;
}

// 1024-point complex forward FFT, radix-4 Stockham. 256 threads, 5 stages,
// result lands in Y. tw[x] = exp(-i*pi*x/1024).
__device__ __forceinline__ void fft1024r4(float2* X, float2* Y,
                                          const float2* __restrict__ tw, int r) {
#pragma unroll
    for (int stg = 0; stg < 5; stg++) {
        int m  = 1 << (2 * stg);
        int q  = r & (m - 1);
        int jm = r - q;
        int base = 4 * jm + q;
        float2 w1 = tw[2 * jm];
        float2 w2 = tw[4 * jm];
        float2 w3 = cmul(w1, w2);
        float2 a0 = X[r], a1 = X[r + 256], a2 = X[r + 512], a3 = X[r + 768];
        float2 b0 = make_float2(a0.x + a2.x, a0.y + a2.y);
        float2 b1 = make_float2(a0.x - a2.x, a0.y - a2.y);
        float2 b2 = make_float2(a1.x + a3.x, a1.y + a3.y);
        float2 b3 = make_float2(a1.x - a3.x, a1.y - a3.y);
        float2 t1 = make_float2(b1.x + b3.y, b1.y - b3.x);
        float2 t3 = make_float2(b1.x - b3.y, b1.y + b3.x);
        Y[base]         = make_float2(b0.x + b2.x, b0.y + b2.y);
        Y[base + m]     = cmul(t1, w1);
        Y[base + 2 * m] = cmul(make_float2(b0.x - b2.x, b0.y - b2.y), w2);
        Y[base + 3 * m] = cmul(t3, w3);
        __syncthreads();
        float2* t = X; X = Y; Y = t;
    }
}

__device__ __forceinline__ float interpC(const float* __restrict__ C, float pos) {
    int lo = (int)floorf(pos);
    lo = min(max(lo, 0), CLEN - 2);
    float frac = pos - (float)lo;
    float clo = C[lo];
    return clo + (C[lo + 1] - clo) * frac;
}

__global__ __launch_bounds__(NTH, 4)
void cheaptrick_kernel(const float* __restrict__ x, const float* __restrict__ f0in,
                       float* __restrict__ out) {
    extern __shared__ char smem[];

    const int tid  = threadIdx.x;
    const int sub  = tid >> 8;
    const int st   = tid & 255;
    const int lane = tid & 31;
    const int w8   = st >> 5;
    const int bx   = blockIdx.x;
    const int b    = blockIdx.y;

    float2* za  = (float2*)(smem)          + sub * 1024;
    float2* zb  = (float2*)(smem + 16384)  + sub * 1024;
    float2* tw  = (float2*)(smem + 32768);
    float*  sP  = (float*)(smem + 40960)   + sub * 1032;
    float*  wex = (float*)(smem + 49216)   + sub * 8;
    float*  red = (float*)(smem + 49280)   + sub * 24;
    float*  scl = (float*)(smem + 49472)   + sub * 4;
    float*  sC  = (float*)(smem)           + sub * 2048;   // aliases za (dead there)
    float*  zaf = (float*)za;
    float*  zbf = (float*)zb;

    int fi = bx * 2 + sub;
    const bool dostore = (fi < NF);
    if (!dostore) fi = NF - 1;

    float f0v = f0in[b * NF + fi];
    if (f0v <= 35.2078239f) f0v = 500.0f;   // F_MIN = 72000/2045

    // twiddle table from global
    for (int r = tid; r < 1024; r += NTH) tw[r] = g_tw[r];

    // -------- frame load + window (rotation recurrence) + sums ---------------
    // zaf[i] = v*w, zbf[i] = w   (no separate frame buffer)
    const float hwl = rintf(36000.0f / f0v);
    float s1 = 0.f, s2 = 0.f, s3 = 0.f;
    {
        float c0, s0, cd, sd;
        sincospif((float)(st - HALF) * f0v * (1.0f / 36000.0f), &s0, &c0);
        sincospif(256.0f * f0v * (1.0f / 36000.0f), &sd, &cd);
#pragma unroll
        for (int ii = 0; ii < 8; ii++) {
            int i = st + ii * 256;
            int rel = i - HALF;
            int ix = min(max(fi * 120 + rel, 0), TLEN - 1);
            float v = x[b * TLEN + ix];
            float w = (fabsf((float)rel) <= hwl) ? fmaf(0.5f, c0, 0.5f) : 0.0f;
            zaf[i] = v * w;
            zbf[i] = w;
            s1 += w; s2 += w * w; s3 += v * w;
            float cn = c0 * cd - s0 * sd;
            s0 = s0 * cd + c0 * sd;
            c0 = cn;
        }
    }
    s1 = warp_sum(s1); s2 = warp_sum(s2); s3 = warp_sum(s3);
    if (lane == 0) { red[w8] = s1; red[8 + w8] = s2; red[16 + w8] = s3; }
    __syncthreads();
    if (st == 0) {
        float a = 0.f, bb = 0.f, c = 0.f;
#pragma unroll
        for (int i = 0; i < 8; i++) { a += red[i]; bb += red[8 + i]; c += red[16 + i]; }
        scl[0] = a; scl[1] = bb; scl[2] = c;
    }
    __syncthreads();
    const float invs = 1.0f / sqrtf(scl[1]);
    const float mu   = scl[2] / scl[0];

    // -------- pack in place: wav = (v*w - mu*w)*invs (same-thread indices) ---
#pragma unroll
    for (int ii = 0; ii < 8; ii++) {
        int i = st + ii * 256;
        zaf[i] = (zaf[i] - mu * zbf[i]) * invs;
    }
    __syncthreads();

    fft1024r4(za, zb, tw, st);          // result in zb

    // -------- untangle rfft -> power spectrum --------------------------------
    for (int k = st; k < 1024; k += SBT) {
        float2 Zk = zb[k];
        float2 Zm = zb[(1024 - k) & 1023];
        float Er = 0.5f * (Zk.x + Zm.x);
        float Ei = 0.5f * (Zk.y - Zm.y);
        float Or = 0.5f * (Zk.y + Zm.y);
        float Oi = 0.5f * (Zm.x - Zk.x);
        float2 w = tw[k];
        float Xr = Er + w.x * Or - w.y * Oi;
        float Xi = Ei + w.x * Oi + w.y * Or;
        sP[k] = Xr * Xr + Xi * Xi;
    }
    if (st == 0) {
        float2 Z0 = zb[0];
        float v = Z0.x - Z0.y;
        sP[1024] = v * v;
    }
    __syncthreads();

    // -------- DC-band replication -------------------------------------------
    const float rate = f0v * (2048.0f / 24000.0f);
    const int  kmax  = (int)floorf(rate);
    float repl = 0.f;
    const bool dorep = (st <= kmax);
    if (dorep) {
        float m = rate - (float)st;
        int lo = (int)floorf(m);
        lo = min(max(lo, 0), K1 - 2);
        float fc = m - (float)lo;
        repl = sP[lo] * (1.f - fc) + sP[lo + 1] * fc;
    }
    __syncthreads();
    if (dorep) sP[st] += repl;
    __syncthreads();

    // -------- reflected cumsum, f32 with mean removal ------------------------
    float meanq;
    {
        const float sclr = 24000.0f / 2048.0f;
        int e0 = st * 5;
        float q0 = 0.f, q1 = 0.f, q2 = 0.f, q3 = 0.f, q4 = 0.f;
        if (e0     < CLEN) q0 = sP[refl_idx(e0)]     * sclr;
        if (e0 + 1 < CLEN) q1 = sP[refl_idx(e0 + 1)] * sclr;
        if (e0 + 2 < CLEN) q2 = sP[refl_idx(e0 + 2)] * sclr;
        if (e0 + 3 < CLEN) q3 = sP[refl_idx(e0 + 3)] * sclr;
        if (e0 + 4 < CLEN) q4 = sP[refl_idx(e0 + 4)] * sclr;

        // pass 1: grand total -> mean
        float tsum = warp_sum(q0 + q1 + q2 + q3 + q4);
        if (lane == 0) red[w8] = tsum;
        __syncthreads();
        if (st == 0) {
            float a = 0.f;
#pragma unroll
            for (int i = 0; i < 8; i++) a += red[i];
            scl[0] = a;
        }
        __syncthreads();
        meanq = scl[0] * (1.0f / (float)CLEN);

        // pass 2: scan of (q - mean) -- zero-mean random walk, small magnitude
        float p0, p1, p2, p3, p4;
        {
            int n0 = (e0     < CLEN);
            int n1 = (e0 + 1 < CLEN);
            int n2 = (e0 + 2 < CLEN);
            int n3 = (e0 + 3 < CLEN);
            int n4 = (e0 + 4 < CLEN);
            p0 = q0 - (n0 ? meanq : 0.f);
            p1 = p0 + q1 - (n1 ? meanq : 0.f);
            p2 = p1 + q2 - (n2 ? meanq : 0.f);
            p3 = p2 + q3 - (n3 ? meanq : 0.f);
            p4 = p3 + q4 - (n4 ? meanq : 0.f);
        }
        float ts = p4, s = ts;
#pragma unroll
        for (int o = 1; o < 32; o <<= 1) {
            float n = __shfl_up_sync(0xffffffffu, s, o);
            if (lane >= o) s += n;
        }
        if (lane == 31) wex[w8] = s;
        __syncthreads();
        if (st == 0) {
            float a = 0.f;
#pragma unroll
            for (int i = 0; i < 8; i++) { float t = wex[i]; wex[i] = a; a += t; }
        }
        __syncthreads();
        float off = wex[w8] + (s - ts);
        if (e0     < CLEN) sC[e0]     = off + p0;
        if (e0 + 1 < CLEN) sC[e0 + 1] = off + p1;
        if (e0 + 2 < CLEN) sC[e0 + 2] = off + p2;
        if (e0 + 3 < CLEN) sC[e0 + 3] = off + p3;
        if (e0 + 4 < CLEN) sC[e0 + 4] = off + p4;
        __syncthreads();
    }

    // -------- f0-adaptive smoothing + log ------------------------------------
    {
        const float wbins    = f0v * (2.0f / 3.0f) * (2048.0f / 24000.0f);
        const float invwidth = 1.0f / (f0v * (2.0f / 3.0f));
        const float linpart  = meanq * wbins;   // restores removed mean (interp is linear)
        for (int k = st; k < K1; k += SBT) {
            float plo = (float)k - 0.5f * wbins + ((float)KPAD - 0.5f);
            float phi = plo + wbins;
            float Ps = (interpC(sC, phi) - interpC(sC, plo) + linpart) * invwidth;
            Ps = fmaxf(Ps, 1e-30f);
            sP[k] = __logf(Ps);
        }
        __syncthreads();
    }

    // -------- cepstrum FFT ---------------------------------------------------
    for (int j = st; j < 1024; j += SBT) {
        int i0 = 2 * j, i1 = 2 * j + 1;
        float g0 = sP[i0 <= HALF ? i0 : FFTL - i0];
        float g1 = sP[i1 <= HALF ? i1 : FFTL - i1];
        za[j] = make_float2(g0, g1);
    }
    __syncthreads();
    fft1024r4(za, zb, tw, st);          // result in zb

    // -------- liftering ------------------------------------------------------
    const float inv2048 = 1.0f / 2048.0f;
    {
        float ls, lc, lds, ldc;
        sincospif(f0v * (float)st * (1.0f / 24000.0f), &ls, &lc);
        sincospif(f0v * 256.0f * (1.0f / 24000.0f), &lds, &ldc);
        const float slf = 24000.0f / (3.14159265358979f * f0v);
#pragma unroll
        for (int ii = 0; ii < 4; ii++) {
            int k = st + ii * 256;
            float2 Zk = zb[k];
            float2 Zm = zb[(1024 - k) & 1023];
            float Er = 0.5f * (Zk.x + Zm.x);
            float Or = 0.5f * (Zk.y + Zm.y);
            float Oi = 0.5f * (Zm.x - Zk.x);
            float2 w = tw[k];
            float Xr = Er + w.x * Or - w.y * Oi;
            float cep = Xr * inv2048;
            float sl = (k == 0) ? 1.0f : ls * slf * g_invk[k];
            float cl = fmaf(0.6f, ls * ls, 1.0f);
            sP[k] = cep * sl * cl;
            float cn = lc * ldc - ls * lds;
            ls = ls * ldc + lc * lds;
            lc = cn;
        }
    }
    if (st == 0) {
        float2 Z0 = zb[0];
        float cep = (Z0.x - Z0.y) * inv2048;
        float z = f0v * 1024.0f * (1.0f / 24000.0f);
        float sn = sinpif(z);
        float sl = sn / (3.14159265358979f * z);
        float cl = fmaf(0.6f, sn * sn, 1.0f);
        sP[1024] = cep * sl * cl;
    }
    __syncthreads();

    // -------- hfft -----------------------------------------------------------
    for (int j = st; j < 1024; j += SBT) {
        int i0 = 2 * j, i1 = 2 * j + 1;
        float g0 = sP[i0 <= HALF ? i0 : FFTL - i0];
        float g1 = sP[i1 <= HALF ? i1 : FFTL - i1];
        za[j] = make_float2(g0, g1);
    }
    __syncthreads();
    fft1024r4(za, zb, tw, st);          // result in zb

    float* op = out + ((size_t)b * NF + fi) * K1;
    for (int k = st; k < 1024; k += SBT) {
        float2 Zk = zb[k];
        float2 Zm = zb[(1024 - k) & 1023];
        float Er = 0.5f * (Zk.x + Zm.x);
        float Or = 0.5f * (Zk.y + Zm.y);
        float Oi = 0.5f * (Zm.x - Zk.x);
        float2 w = tw[k];
        if (dostore) op[k] = Er + w.x * Or - w.y * Oi;
    }
    if (st == 0 && dostore) {
        float2 Z0 = zb[0];
        op[1024] = Z0.x - Z0.y;
    }
}

extern "C" void kernel_launch(void* const* d_in, const int* in_sizes, int n_in,
                              void* d_out, int out_size) {
    (void)in_sizes; (void)n_in; (void)out_size;
    const float* x  = (const float*)d_in[0];
    const float* f0 = (const float*)d_in[1];
    float* out = (float*)d_out;
    init_tables<<<5, 256>>>();
    cudaFuncSetAttribute(cheaptrick_kernel,
                         cudaFuncAttributeMaxDynamicSharedMemorySize, SMEM_BYTES);
    dim3 grid((NF + 1) / 2, BATCH);
    cheaptrick_kernel<<<grid, NTH, SMEM_BYTES>>>(x, f0, out);
}

// round 5
// speedup vs baseline: 2.3681x; 1.1138x over previous
#include <cuda_runtime.h>
#include <math.h>

#define BATCH 8
#define TLEN 120000
#define NF 1001
#define FFTL 2048
#define HALF 1024
#define K1 1025
#define KPAD 36
#define CLEN 1097          /* K1 + 2*KPAD */
#define NTH 512
#define SBT 256            /* threads per sub-block (frame) */

/* dynamic smem layout (bytes):
   za  float2[2][1024] @ 0      (16384)
   zb  float2[2][1024] @ 16384  (16384)  -- sC float[1097] aliases this later
   tw  float2[1024]    @ 32768  (8192)
   sP  float[2][1032]  @ 40960  (8256)
   wex float[2][8]     @ 49216  (64)
   red float[2][24]    @ 49280  (192)
   scl float[2][4]     @ 49472  (32)
   total 49504 -> 4 CTAs/SM */
#define SMEM_BYTES 49504

__device__ float2 g_tw[1024];
__device__ float  g_invk[1025];

__global__ void init_tables() {
    int i = blockIdx.x * blockDim.x + threadIdx.x;
    if (i < 1024) {
        float s, c;
        sincospif(-(float)i * (1.0f / 1024.0f), &s, &c);
        g_tw[i] = make_float2(c, s);
    }
    if (i <= 1024) g_invk[i] = (i == 0) ? 0.0f : 1.0f / (float)i;
}

__device__ __forceinline__ float warp_sum(float v) {
#pragma unroll
    for (int o = 16; o; o >>= 1) v += __shfl_down_sync(0xffffffffu, v, o);
    return v;
}

__device__ __forceinline__ float2 cmul(float2 a, float2 b) {
    return make_float2(a.x * b.x - a.y * b.y, a.x * b.y + a.y * b.x);
}

__device__ __forceinline__ int refl_idx(int t) {
    int j = t - KPAD;
    int r = j < 0 ? -j : j;
    if (r > HALF) r = FFTL - r;
    return r;
}

// Scatter value c[k] of the even-extended real sequence into the packed
// complex input buffer: zaf[2j+p] = c[ext(2j+p)], ext(i) = i<=1024 ? i : 2048-i.
__device__ __forceinline__ void scatter_even(float* zaf, int k, float v) {
    int j1 = k >> 1;
    if (k & 1) {
        zaf[2 * j1 + 1] = v;
        int j2 = 1023 - j1;
        zaf[2 * j2 + 1] = v;
    } else {
        zaf[2 * j1] = v;
        int j2 = 1024 - j1;
        if (j2 < 1024 && j2 != j1) zaf[2 * j2] = v;
    }
}

// 1024-point complex forward FFT, radix-4 Stockham. 256 threads, 5 stages,
// result lands in Y. tw[x] = exp(-i*pi*x/1024). w2 = w1^2 in registers.
__device__ __forceinline__ void fft1024r4(float2* X, float2* Y,
                                          const float2* __restrict__ tw, int r) {
#pragma unroll
    for (int stg = 0; stg < 5; stg++) {
        int m  = 1 << (2 * stg);
        int q  = r & (m - 1);
        int jm = r - q;
        int base = 4 * jm + q;
        float2 w1 = tw[2 * jm];
        float2 w2 = make_float2(w1.x * w1.x - w1.y * w1.y, 2.0f * w1.x * w1.y);
        float2 w3 = cmul(w1, w2);
        float2 a0 = X[r], a1 = X[r + 256], a2 = X[r + 512], a3 = X[r + 768];
        float2 b0 = make_float2(a0.x + a2.x, a0.y + a2.y);
        float2 b1 = make_float2(a0.x - a2.x, a0.y - a2.y);
        float2 b2 = make_float2(a1.x + a3.x, a1.y + a3.y);
        float2 b3 = make_float2(a1.x - a3.x, a1.y - a3.y);
        float2 t1 = make_float2(b1.x + b3.y, b1.y - b3.x);
        float2 t3 = make_float2(b1.x - b3.y, b1.y + b3.x);
        Y[base]         = make_float2(b0.x + b2.x, b0.y + b2.y);
        Y[base + m]     = cmul(t1, w1);
        Y[base + 2 * m] = cmul(make_float2(b0.x - b2.x, b0.y - b2.y), w2);
        Y[base + 3 * m] = cmul(t3, w3);
        __syncthreads();
        float2* t = X; X = Y; Y = t;
    }
}

__device__ __forceinline__ float interpC(const float* __restrict__ C, float pos) {
    int lo = (int)floorf(pos);
    lo = min(max(lo, 0), CLEN - 2);
    float frac = pos - (float)lo;
    float clo = C[lo];
    return clo + (C[lo + 1] - clo) * frac;
}

__global__ __launch_bounds__(NTH, 4)
void cheaptrick_kernel(const float* __restrict__ x, const float* __restrict__ f0in,
                       float* __restrict__ out) {
    extern __shared__ char smem[];

    const int tid  = threadIdx.x;
    const int sub  = tid >> 8;
    const int st   = tid & 255;
    const int lane = tid & 31;
    const int w8   = st >> 5;
    const int bx   = blockIdx.x;
    const int b    = blockIdx.y;

    float2* za  = (float2*)(smem)          + sub * 1024;
    float2* zb  = (float2*)(smem + 16384)  + sub * 1024;
    float2* tw  = (float2*)(smem + 32768);
    float*  sP  = (float*)(smem + 40960)   + sub * 1032;
    float*  wex = (float*)(smem + 49216)   + sub * 8;
    float*  red = (float*)(smem + 49280)   + sub * 24;
    float*  scl = (float*)(smem + 49472)   + sub * 4;
    float*  sC  = (float*)(smem + 16384)   + sub * 2048;   // aliases zb (dead there)
    float*  zaf = (float*)za;

    int fi = bx * 2 + sub;
    const bool dostore = (fi < NF);
    if (!dostore) fi = NF - 1;

    float f0v = f0in[b * NF + fi];
    if (f0v <= 35.2078239f) f0v = 500.0f;   // F_MIN = 72000/2045

    // twiddle table from global
    for (int r = tid; r < 1024; r += NTH) tw[r] = g_tw[r];

    // -------- frame load + window (rotation recurrence) + sums ---------------
    const float hwl = rintf(36000.0f / f0v);
    float cb, sb, cd, sd;
    sincospif((float)(st - HALF) * f0v * (1.0f / 36000.0f), &sb, &cb);
    sincospif(256.0f * f0v * (1.0f / 36000.0f), &sd, &cd);
    float s1 = 0.f, s2 = 0.f, s3 = 0.f;
    {
        float c0 = cb, s0 = sb;
#pragma unroll
        for (int ii = 0; ii < 8; ii++) {
            int i = st + ii * 256;
            int rel = i - HALF;
            int ix = min(max(fi * 120 + rel, 0), TLEN - 1);
            float v = x[b * TLEN + ix];
            float w = (fabsf((float)rel) <= hwl) ? fmaf(0.5f, c0, 0.5f) : 0.0f;
            zaf[i] = v * w;
            s1 += w; s2 += w * w; s3 += v * w;
            float cn = c0 * cd - s0 * sd;
            s0 = s0 * cd + c0 * sd;
            c0 = cn;
        }
    }
    s1 = warp_sum(s1); s2 = warp_sum(s2); s3 = warp_sum(s3);
    if (lane == 0) { red[w8] = s1; red[8 + w8] = s2; red[16 + w8] = s3; }
    __syncthreads();
    if (st == 0) {
        float a = 0.f, bb = 0.f, c = 0.f;
#pragma unroll
        for (int i = 0; i < 8; i++) { a += red[i]; bb += red[8 + i]; c += red[16 + i]; }
        scl[0] = a; scl[1] = bb; scl[2] = c;
    }
    __syncthreads();
    const float invs = 1.0f / sqrtf(scl[1]);
    const float mu   = scl[2] / scl[0];

    // -------- pack in place: wav = (v*w - mu*w)*invs (w replayed from regs) --
    {
        float c0 = cb, s0 = sb;
#pragma unroll
        for (int ii = 0; ii < 8; ii++) {
            int i = st + ii * 256;
            int rel = i - HALF;
            float w = (fabsf((float)rel) <= hwl) ? fmaf(0.5f, c0, 0.5f) : 0.0f;
            zaf[i] = (zaf[i] - mu * w) * invs;
            float cn = c0 * cd - s0 * sd;
            s0 = s0 * cd + c0 * sd;
            c0 = cn;
        }
    }
    __syncthreads();

    fft1024r4(za, zb, tw, st);          // result in zb

    // -------- paired untangle -> power spectrum P[0..1024] -------------------
#pragma unroll
    for (int ii = 0; ii < 2; ii++) {
        int k = st + ii * 256;
        float2 Zk = zb[k];
        float2 Zm = zb[(1024 - k) & 1023];
        float Er = 0.5f * (Zk.x + Zm.x);
        float Ei = 0.5f * (Zk.y - Zm.y);
        float Or = 0.5f * (Zk.y + Zm.y);
        float Oi = 0.5f * (Zm.x - Zk.x);
        float2 w = tw[k];
        float u = w.x * Or - w.y * Oi;
        float t = w.x * Oi + w.y * Or;
        float XrP = Er + u, XiP = Ei + t;
        float XrM = Er - u, XiM = Ei - t;
        sP[k]        = XrP * XrP + XiP * XiP;
        sP[1024 - k] = XrM * XrM + XiM * XiM;
    }
    if (st == 0) { float2 Z = zb[512]; sP[512] = Z.x * Z.x + Z.y * Z.y; }
    __syncthreads();

    // -------- DC-band replication -------------------------------------------
    const float rate = f0v * (2048.0f / 24000.0f);
    const int  kmax  = (int)floorf(rate);
    float repl = 0.f;
    const bool dorep = (st <= kmax);
    if (dorep) {
        float m = rate - (float)st;
        int lo = (int)floorf(m);
        lo = min(max(lo, 0), K1 - 2);
        float fc = m - (float)lo;
        repl = sP[lo] * (1.f - fc) + sP[lo + 1] * fc;
    }
    __syncthreads();
    if (dorep) sP[st] += repl;
    __syncthreads();

    // -------- reflected cumsum, f32 with mean removal (sC aliases zb) --------
    float meanq;
    {
        const float sclr = 24000.0f / 2048.0f;
        int e0 = st * 5;
        float q0 = 0.f, q1 = 0.f, q2 = 0.f, q3 = 0.f, q4 = 0.f;
        if (e0     < CLEN) q0 = sP[refl_idx(e0)]     * sclr;
        if (e0 + 1 < CLEN) q1 = sP[refl_idx(e0 + 1)] * sclr;
        if (e0 + 2 < CLEN) q2 = sP[refl_idx(e0 + 2)] * sclr;
        if (e0 + 3 < CLEN) q3 = sP[refl_idx(e0 + 3)] * sclr;
        if (e0 + 4 < CLEN) q4 = sP[refl_idx(e0 + 4)] * sclr;

        float tsum = warp_sum(q0 + q1 + q2 + q3 + q4);
        if (lane == 0) red[w8] = tsum;
        __syncthreads();
        if (st == 0) {
            float a = 0.f;
#pragma unroll
            for (int i = 0; i < 8; i++) a += red[i];
            scl[0] = a;
        }
        __syncthreads();
        meanq = scl[0] * (1.0f / (float)CLEN);

        float p0, p1, p2, p3, p4;
        {
            int n0 = (e0     < CLEN);
            int n1 = (e0 + 1 < CLEN);
            int n2 = (e0 + 2 < CLEN);
            int n3 = (e0 + 3 < CLEN);
            int n4 = (e0 + 4 < CLEN);
            p0 = q0 - (n0 ? meanq : 0.f);
            p1 = p0 + q1 - (n1 ? meanq : 0.f);
            p2 = p1 + q2 - (n2 ? meanq : 0.f);
            p3 = p2 + q3 - (n3 ? meanq : 0.f);
            p4 = p3 + q4 - (n4 ? meanq : 0.f);
        }
        float ts = p4, s = ts;
#pragma unroll
        for (int o = 1; o < 32; o <<= 1) {
            float n = __shfl_up_sync(0xffffffffu, s, o);
            if (lane >= o) s += n;
        }
        if (lane == 31) wex[w8] = s;
        __syncthreads();
        if (st == 0) {
            float a = 0.f;
#pragma unroll
            for (int i = 0; i < 8; i++) { float t = wex[i]; wex[i] = a; a += t; }
        }
        __syncthreads();
        float off = wex[w8] + (s - ts);
        if (e0     < CLEN) sC[e0]     = off + p0;
        if (e0 + 1 < CLEN) sC[e0 + 1] = off + p1;
        if (e0 + 2 < CLEN) sC[e0 + 2] = off + p2;
        if (e0 + 3 < CLEN) sC[e0 + 3] = off + p3;
        if (e0 + 4 < CLEN) sC[e0 + 4] = off + p4;
        __syncthreads();
    }

    // -------- smoothing + log, scattered directly into za (even extension) ---
    {
        const float wbins    = f0v * (2.0f / 3.0f) * (2048.0f / 24000.0f);
        const float invwidth = 1.0f / (f0v * (2.0f / 3.0f));
        const float linpart  = meanq * wbins;
        for (int k = st; k < K1; k += SBT) {
            float plo = (float)k - 0.5f * wbins + ((float)KPAD - 0.5f);
            float phi = plo + wbins;
            float Ps = (interpC(sC, phi) - interpC(sC, plo) + linpart) * invwidth;
            Ps = fmaxf(Ps, 1e-30f);
            scatter_even(zaf, k, __logf(Ps));
        }
        __syncthreads();
    }

    fft1024r4(za, zb, tw, st);          // cepstrum FFT, result in zb

    // -------- paired lifter untangle, scattered directly into za -------------
    const float inv2048 = 1.0f / 2048.0f;
    {
        float ls, lc, lds, ldc, sA, cA;
        sincospif(f0v * (float)st * (1.0f / 24000.0f), &ls, &lc);
        sincospif(f0v * 256.0f * (1.0f / 24000.0f), &lds, &ldc);
        sincospif(f0v * 1024.0f * (1.0f / 24000.0f), &sA, &cA);
        const float slf = 24000.0f / (3.14159265358979f * f0v);
#pragma unroll
        for (int ii = 0; ii < 2; ii++) {
            int k = st + ii * 256;
            float2 Zk = zb[k];
            float2 Zm = zb[(1024 - k) & 1023];
            float Er = 0.5f * (Zk.x + Zm.x);
            float Or = 0.5f * (Zk.y + Zm.y);
            float Oi = 0.5f * (Zm.x - Zk.x);
            float2 w = tw[k];
            float u = w.x * Or - w.y * Oi;
            float cepP = (Er + u) * inv2048;
            float cepM = (Er - u) * inv2048;
            float slcl = (k == 0) ? 1.0f
                        : ls * slf * g_invk[k] * fmaf(0.6f, ls * ls, 1.0f);
            scatter_even(zaf, k, cepP * slcl);
            int kp = 1024 - k;
            float lsp = sA * lc - cA * ls;                 // sin(pi*(A - z))
            float slclp = lsp * slf * g_invk[kp] * fmaf(0.6f, lsp * lsp, 1.0f);
            scatter_even(zaf, kp, cepM * slclp);
            float cn = lc * ldc - ls * lds;
            ls = ls * ldc + lc * lds;
            lc = cn;
        }
        if (st == 0) {
            float cep = zb[512].x * inv2048;
            float l5 = sinpif(f0v * 512.0f * (1.0f / 24000.0f));
            float slcl = l5 * slf * g_invk[512] * fmaf(0.6f, l5 * l5, 1.0f);
            scatter_even(zaf, 512, cep * slcl);
        }
    }
    __syncthreads();

    fft1024r4(za, zb, tw, st);          // hfft, result in zb

    // -------- paired final untangle -> output --------------------------------
    float* op = out + ((size_t)b * NF + fi) * K1;
#pragma unroll
    for (int ii = 0; ii < 2; ii++) {
        int k = st + ii * 256;
        float2 Zk = zb[k];
        float2 Zm = zb[(1024 - k) & 1023];
        float Er = 0.5f * (Zk.x + Zm.x);
        float Or = 0.5f * (Zk.y + Zm.y);
        float Oi = 0.5f * (Zm.x - Zk.x);
        float2 w = tw[k];
        float u = w.x * Or - w.y * Oi;
        if (dostore) {
            op[k]        = Er + u;
            op[1024 - k] = Er - u;
        }
    }
    if (st == 0 && dostore) op[512] = zb[512].x;
}

extern "C" void kernel_launch(void* const* d_in, const int* in_sizes, int n_in,
                              void* d_out, int out_size) {
    (void)in_sizes; (void)n_in; (void)out_size;
    const float* x  = (const float*)d_in[0];
    const float* f0 = (const float*)d_in[1];
    float* out = (float*)d_out;
    init_tables<<<5, 256>>>();
    cudaFuncSetAttribute(cheaptrick_kernel,
                         cudaFuncAttributeMaxDynamicSharedMemorySize, SMEM_BYTES);
    dim3 grid((NF + 1) / 2, BATCH);
    cheaptrick_kernel<<<grid, NTH, SMEM_BYTES>>>(x, f0, out);
}